// round 16
// baseline (speedup 1.0000x reference)
#include <cuda_runtime.h>

// ---------------- problem constants ----------------
#define BATCH 2
#define CH    3
#define IMGH  384
#define IMGW  384
#define IMGPIX (IMGH*IMGW)
#define NB1   576   // blocks per batch in the p=1 stage (24*24)

// ---------------- scratch (device globals; no allocations allowed) ----------
// inter-stage tensors stored channel-interleaved: float4 {c0,c1,c2,0} per pixel
__device__ float4 g_x3v[BATCH*IMGPIX];
__device__ float4 g_x6v[BATCH*IMGPIX];
__device__ float4 g_x9v[BATCH*IMGPIX];
__device__ float g_bmax[BATCH*NB1];

// folded weights (written by attn1 blocks (0,0)/(1,0), read by attn2/attn3)
__device__ float4 g_G6t [4*12*12/4];   // [h][m][n], n padded to DP=12
__device__ float4 g_Wv6t[4*12*12/4];
__device__ float4 g_gb6 [4*12/4];
__device__ float4 g_bv6 [4*12/4];
__device__ float4 g_G9t [2*27*28/4];   // DP=28
__device__ float4 g_Wv9t[2*27*28/4];
__device__ float4 g_gb9 [2*28/4];
__device__ float4 g_bv9 [2*28/4];

// ---------------- per-process stream/event context (no device allocations) --
struct PipeCtx {
    cudaStream_t s1;
    cudaEvent_t evFork, evJoin;
    PipeCtx() {
        cudaStreamCreateWithFlags(&s1, cudaStreamNonBlocking);
        cudaEventCreateWithFlags(&evFork, cudaEventDisableTiming);
        cudaEventCreateWithFlags(&evJoin, cudaEventDisableTiming);
    }
};
static PipeCtx g_pipe;

__device__ __forceinline__ float neg_inf() { return __int_as_float(0xff800000); }

__device__ __forceinline__ int reflect_h(int r) {
    if (r < 0) r = -r; else if (r >= IMGH) r = 2 * IMGH - 2 - r; return r;
}
__device__ __forceinline__ int reflect_w(int c) {
    if (c < 0) c = -c; else if (c >= IMGW) c = 2 * IMGW - 2 - c; return c;
}

// ---------------- weight folding (runs inside attn1 on 2 blocks/launch) -----
__device__ void fold_weights(const float* __restrict__ Wq, const float* __restrict__ bq,
                             const float* __restrict__ Wk,
                             const float* __restrict__ Wv, const float* __restrict__ bv,
                             const float* __restrict__ hw,
                             float* Gt, float* gbp, float* Wvt, float* bvp,
                             int H, int D, int DP, int tid, int nthr)
{
    float scale = rsqrtf((float)D);
    for (int i = tid; i < H * D * DP; i += nthr) {
        int h = i / (D * DP); int r = i % (D * DP); int m = r / DP; int n = r % DP;
        float g = 0.f, wvv = 0.f;
        if (n < D) {
            const float* wk = Wk + h * D * D;
            const float* wq = Wq + h * D * D;
            float s = 0.f;
            for (int e = 0; e < D; e++) s += wk[e * D + n] * wq[e * D + m];
            g   = s * scale;
            wvv = hw[h] * Wv[h * D * D + n * D + m];
        }
        Gt[i] = g; Wvt[i] = wvv;
    }
    for (int i = tid; i < H * DP; i += nthr) {
        int h = i / DP, n = i % DP;
        float gb = 0.f, bvv = 0.f;
        if (n < D) {
            const float* wk = Wk + h * D * D;
            float s = 0.f;
            for (int e = 0; e < D; e++) s += bq[h * D + e] * wk[e * D + n];
            gb  = s * scale;
            bvv = hw[h] * bv[h * D + n];
        }
        gbp[i] = gb; bvp[i] = bvv;
    }
}

// ============================================================================
// p=1 stage (per-batch launch): one thread per window; 9 neighbor tokens
// register-cached; 6 heads in 2 sequential groups; two-pass softmax.
// Output channel-interleaved (1 STG.128 per window).
// Blocks (0,0) and (1,0) fold p=2 / p=3 weights. Computes per-block image max.
// ============================================================================
#define A1_TW 16
#define A1_TH 16
__global__ void __launch_bounds__(A1_TW*A1_TH)
attn1_kernel(int bbase,
             const float* __restrict__ in, float4* __restrict__ out4,
             const float* __restrict__ Wq, const float* __restrict__ bq,
             const float* __restrict__ Wk,
             const float* __restrict__ Wv, const float* __restrict__ bv,
             const float* __restrict__ hw,
             const float* __restrict__ w6q, const float* __restrict__ b6q,
             const float* __restrict__ w6k, const float* __restrict__ w6v,
             const float* __restrict__ b6v, const float* __restrict__ hw6,
             const float* __restrict__ w9q, const float* __restrict__ b9q,
             const float* __restrict__ w9k, const float* __restrict__ w9v,
             const float* __restrict__ b9v, const float* __restrict__ hw9)
{
    constexpr int D = 3, HEADS = 6, HPG = 3, DP = 4;
    constexpr int NTHR  = A1_TW * A1_TH;          // 256
    constexpr int TILEH = A1_TH + 2;              // 18
    constexpr int TILEW = A1_TW + 2;              // 18
    constexpr int ELEMS = TILEH * TILEW;          // 324

    __shared__ __align__(16) float4 s_t4[TILEH * TILEW];
    __shared__ __align__(16) float s_Gt [HEADS * D * DP];
    __shared__ __align__(16) float s_Wvt[HEADS * D * DP];
    __shared__ __align__(16) float s_gbp[HEADS * DP];
    __shared__ __align__(16) float s_bvp[HEADS * DP];
    __shared__ float s_red[NTHR / 32];

    const int tid = threadIdx.x;
    const int b   = bbase;
    const int wi0 = blockIdx.y * A1_TH;
    const int wj0 = blockIdx.x * A1_TW;
    const float scale = rsqrtf((float)D);

    if (blockIdx.y == 0) {
        if (blockIdx.x == 0)
            fold_weights(w6q, b6q, w6k, w6v, b6v, hw6,
                         (float*)g_G6t, (float*)g_gb6, (float*)g_Wv6t, (float*)g_bv6,
                         4, 12, 12, tid, NTHR);
        else if (blockIdx.x == 1)
            fold_weights(w9q, b9q, w9k, w9v, b9v, hw9,
                         (float*)g_G9t, (float*)g_gb9, (float*)g_Wv9t, (float*)g_bv9,
                         2, 27, 28, tid, NTHR);
    }

    for (int i = tid; i < HEADS * D * DP; i += NTHR) {
        int h = i / (D * DP); int r = i % (D * DP); int m = r / DP; int n = r % DP;
        float g = 0.f, wvv = 0.f;
        if (n < D) {
            const float* wk = Wk + h * D * D;
            const float* wq = Wq + h * D * D;
            float s = 0.f;
            #pragma unroll
            for (int e = 0; e < D; e++) s += wk[e * D + n] * wq[e * D + m];
            g   = s * scale;
            wvv = hw[h] * Wv[h * D * D + n * D + m];
        }
        s_Gt[i] = g; s_Wvt[i] = wvv;
    }
    for (int i = tid; i < HEADS * DP; i += NTHR) {
        int h = i / DP, n = i % DP;
        float gb = 0.f, bvv = 0.f;
        if (n < D) {
            const float* wk = Wk + h * D * D;
            float s = 0.f;
            #pragma unroll
            for (int e = 0; e < D; e++) s += bq[h * D + e] * wk[e * D + n];
            gb  = s * scale;
            bvv = hw[h] * bv[h * D + n];
        }
        s_gbp[i] = gb; s_bvp[i] = bvv;
    }

    // ---- tile load: per-thread indices hoisted out of the channel loop ----
    const float* inb = in + (size_t)b * CH * IMGPIX;
    float lmax = neg_inf();
    {
        int i0 = tid;
        int tr0 = i0 / TILEW, tc0 = i0 % TILEW;
        int off0 = reflect_h(wi0 - 1 + tr0) * IMGW + reflect_w(wj0 - 1 + tc0);
        int i1 = tid + NTHR;
        int tr1 = i1 / TILEW, tc1 = i1 % TILEW;
        bool v1 = (i1 < ELEMS);
        int off1 = v1 ? reflect_h(wi0 - 1 + tr1) * IMGW + reflect_w(wj0 - 1 + tc1) : 0;

        float4 p0, p1;
        float a;
        a = inb[0 * IMGPIX + off0]; p0.x = a; lmax = fmaxf(lmax, a);
        a = inb[1 * IMGPIX + off0]; p0.y = a; lmax = fmaxf(lmax, a);
        a = inb[2 * IMGPIX + off0]; p0.z = a; lmax = fmaxf(lmax, a);
        p0.w = 0.f;
        s_t4[i0] = p0;
        if (v1) {
            a = inb[0 * IMGPIX + off1]; p1.x = a; lmax = fmaxf(lmax, a);
            a = inb[1 * IMGPIX + off1]; p1.y = a; lmax = fmaxf(lmax, a);
            a = inb[2 * IMGPIX + off1]; p1.z = a; lmax = fmaxf(lmax, a);
            p1.w = 0.f;
            s_t4[i1] = p1;
        }
    }
    #pragma unroll
    for (int o = 16; o; o >>= 1) lmax = fmaxf(lmax, __shfl_xor_sync(0xffffffffu, lmax, o));
    if ((tid & 31) == 0) s_red[tid >> 5] = lmax;
    __syncthreads();
    if (tid == 0) {
        float m = s_red[0];
        #pragma unroll
        for (int w = 1; w < NTHR / 32; w++) m = fmaxf(m, s_red[w]);
        g_bmax[b * NB1 + blockIdx.y * gridDim.x + blockIdx.x] = m;
    }

    const int lwj = tid % A1_TW;
    const int lwi = tid / A1_TW;

    // ---- register-cache the 9 neighbor tokens (one LDS.128 each) ----
    float4 tk[9];
    #pragma unroll
    for (int di = 0; di < 3; di++)
        #pragma unroll
        for (int dj = 0; dj < 3; dj++)
            tk[di * 3 + dj] = s_t4[(lwi + di) * TILEW + (lwj + dj)];

    const float4 ctr = tk[4];
    float tok4[D] = {ctr.x, ctr.y, ctr.z};

    float part[DP] = {0.f, 0.f, 0.f, 0.f};

    // ---- 2 sequential head-groups of 3 heads each (two-pass softmax) ----
    #pragma unroll
    for (int g = 0; g < 2; g++) {
        const int h0 = g * HPG;

        float u[HPG][DP];
        #pragma unroll
        for (int h = 0; h < HPG; h++) {
            float4 v = *(const float4*)&s_gbp[(h0 + h) * DP];
            u[h][0] = v.x; u[h][1] = v.y; u[h][2] = v.z; u[h][3] = v.w;
        }
        #pragma unroll
        for (int h = 0; h < HPG; h++)
            #pragma unroll
            for (int m = 0; m < D; m++) {
                float4 gg = *(const float4*)&s_Gt[((h0 + h) * D + m) * DP];
                float t = tok4[m];
                u[h][0] += gg.x * t; u[h][1] += gg.y * t; u[h][2] += gg.z * t; u[h][3] += gg.w * t;
            }

        float sc[HPG][9], smax[HPG];
        #pragma unroll
        for (int h = 0; h < HPG; h++) smax[h] = neg_inf();

        #pragma unroll
        for (int t = 0; t < 9; t++) {
            float4 v = tk[t];
            #pragma unroll
            for (int h = 0; h < HPG; h++) {
                float s = u[h][0] * v.x + u[h][1] * v.y + u[h][2] * v.z;
                sc[h][t] = s; smax[h] = fmaxf(smax[h], s);
            }
        }

        #pragma unroll
        for (int h = 0; h < HPG; h++) {
            float den = 0.f;
            #pragma unroll
            for (int t = 0; t < 9; t++) { float e = __expf(sc[h][t] - smax[h]); sc[h][t] = e; den += e; }
            float inv = 1.f / den;
            #pragma unroll
            for (int t = 0; t < 9; t++) sc[h][t] *= inv;
        }

        float acc[HPG][D];
        #pragma unroll
        for (int h = 0; h < HPG; h++)
            #pragma unroll
            for (int d = 0; d < D; d++) acc[h][d] = 0.f;

        #pragma unroll
        for (int t = 0; t < 9; t++) {
            float4 v = tk[t];
            #pragma unroll
            for (int h = 0; h < HPG; h++) {
                acc[h][0] += sc[h][t] * v.x;
                acc[h][1] += sc[h][t] * v.y;
                acc[h][2] += sc[h][t] * v.z;
            }
        }

        #pragma unroll
        for (int h = 0; h < HPG; h++) {
            float4 bvv = *(const float4*)&s_bvp[(h0 + h) * DP];
            part[0] += bvv.x; part[1] += bvv.y; part[2] += bvv.z; part[3] += bvv.w;
            #pragma unroll
            for (int m = 0; m < D; m++) {
                float4 wv = *(const float4*)&s_Wvt[((h0 + h) * D + m) * DP];
                float a = acc[h][m];
                part[0] += wv.x * a; part[1] += wv.y * a; part[2] += wv.z * a; part[3] += wv.w * a;
            }
        }
    }

    const int wi = wi0 + lwi, wj = wj0 + lwj;
    out4[(size_t)b * IMGPIX + wi * IMGW + wj] = make_float4(part[0], part[1], part[2], 0.f);
}

// ============================================================================
// p=2 stage (per-batch launch): one warp-group per head; float2-word rotated
// tile sourced from channel-interleaved float4. SINGLE-PASS softmax: each
// token is read from smem ONCE (halves the dominant LDS stream; kernel is
// LDS-throughput-bound at L1~58%). No max-subtraction: scores are tiny
// (|s| <~ 1), softmax is shift-invariant, __expf is safe.
// ============================================================================
template<int TILEH>
__device__ __forceinline__ int sm_idx2w(int c,int r,int wc){ // float2-word index
    int wcs = (wc + (((r >> 1) & 3) << 2)) & 15;
    return (c * TILEH + r) * 16 + wcs;
}

#define A2_TW 8
#define A2_TH 8
__global__ void __launch_bounds__(A2_TW*A2_TH*4)
attn2_kernel(int bbase,
             const float4* __restrict__ in4, float4* __restrict__ out4,
             const float4* __restrict__ Gt, const float4* __restrict__ gbp,
             const float4* __restrict__ Wvt, const float4* __restrict__ bvp)
{
    constexpr int P = 2, D = 12, HEADS = 4;
    constexpr int DP = 12, DP4 = 3;
    constexpr int DR = 13;
    constexpr int NW = A2_TW * A2_TH;          // 64
    constexpr int NTHR = NW * HEADS;           // 256
    constexpr int TILEH = (A2_TH + 2) * P;     // 20
    constexpr int TILEW = (A2_TW + 2) * P;     // 20
    constexpr int ELEMS = TILEH * TILEW;       // 400
    constexpr int CPLANE = TILEH * 32;

    __shared__ __align__(16) float s_tile[CH * CPLANE];
    __shared__ float s_part[(HEADS - 1) * NW * DR];

    const int tid = threadIdx.x;
    const int b   = bbase;
    const int wi0 = blockIdx.y * A2_TH;
    const int wj0 = blockIdx.x * A2_TW;

    const float4* inb = in4 + (size_t)b * IMGPIX;
    {
        int i0 = tid;
        int tr0 = i0 / TILEW, tc0 = i0 % TILEW;
        int off0 = reflect_h((wi0 - 1) * P + tr0) * IMGW + reflect_w((wj0 - 1) * P + tc0);
        int sm0  = sm_idx2w<TILEH>(0, tr0, tc0 >> 1) * 2 + (tc0 & 1);
        float4 v0 = inb[off0];
        s_tile[sm0] = v0.x;
        s_tile[CPLANE + sm0] = v0.y;
        s_tile[2 * CPLANE + sm0] = v0.z;

        int i1 = tid + NTHR;
        if (i1 < ELEMS) {
            int tr1 = i1 / TILEW, tc1 = i1 % TILEW;
            int off1 = reflect_h((wi0 - 1) * P + tr1) * IMGW + reflect_w((wj0 - 1) * P + tc1);
            int sm1  = sm_idx2w<TILEH>(0, tr1, tc1 >> 1) * 2 + (tc1 & 1);
            float4 v1 = inb[off1];
            s_tile[sm1] = v1.x;
            s_tile[CPLANE + sm1] = v1.y;
            s_tile[2 * CPLANE + sm1] = v1.z;
        }
    }
    __syncthreads();

    const int w   = tid % NW;
    const int h   = tid / NW;
    const int lwj = w % A2_TW;
    const int lwi = w / A2_TW;

    // ---- center token (for u) ----
    float tok4[D];
    #pragma unroll
    for (int c = 0; c < CH; c++)
        #pragma unroll
        for (int pi = 0; pi < 2; pi++) {
            float2 v = ((const float2*)s_tile)[sm_idx2w<TILEH>(c, (lwi + 1) * 2 + pi, lwj + 1)];
            tok4[c * 4 + pi * 2] = v.x; tok4[c * 4 + pi * 2 + 1] = v.y;
        }

    float u[DP];
    #pragma unroll
    for (int e4 = 0; e4 < DP4; e4++) {
        float4 v = gbp[h * DP4 + e4];
        u[e4*4] = v.x; u[e4*4+1] = v.y; u[e4*4+2] = v.z; u[e4*4+3] = v.w;
    }
    #pragma unroll
    for (int m = 0; m < D; m++) {
        float t = tok4[m];
        #pragma unroll
        for (int e4 = 0; e4 < DP4; e4++) {
            float4 g = Gt[(h * D + m) * DP4 + e4];
            u[e4*4]   += g.x * t; u[e4*4+1] += g.y * t;
            u[e4*4+2] += g.z * t; u[e4*4+3] += g.w * t;
        }
    }

    // ---- single pass over the 9 tokens: load once, score, exp, accumulate ----
    float den = 0.f;
    float acc[D];
    #pragma unroll
    for (int d = 0; d < D; d++) acc[d] = 0.f;

    #pragma unroll
    for (int di = 0; di < 3; di++)
    #pragma unroll
    for (int dj = 0; dj < 3; dj++) {
        float t0[D];
        #pragma unroll
        for (int c = 0; c < CH; c++)
            #pragma unroll
            for (int pi = 0; pi < 2; pi++) {
                float2 v = ((const float2*)s_tile)[sm_idx2w<TILEH>(c, (lwi + di) * 2 + pi, lwj + dj)];
                t0[c * 4 + pi * 2] = v.x; t0[c * 4 + pi * 2 + 1] = v.y;
            }
        float s = 0.f;
        #pragma unroll
        for (int e = 0; e < D; e++) s += u[e] * t0[e];
        float ex = __expf(s);
        den += ex;
        #pragma unroll
        for (int e = 0; e < D; e++) acc[e] += ex * t0[e];
    }

    float inv = 1.f / den;
    float part[DP];
    #pragma unroll
    for (int e4 = 0; e4 < DP4; e4++) {
        float4 v = bvp[h * DP4 + e4];
        part[e4*4] = v.x; part[e4*4+1] = v.y; part[e4*4+2] = v.z; part[e4*4+3] = v.w;
    }
    #pragma unroll
    for (int m = 0; m < D; m++) {
        float a = acc[m] * inv;
        #pragma unroll
        for (int e4 = 0; e4 < DP4; e4++) {
            float4 wv = Wvt[(h * D + m) * DP4 + e4];
            part[e4*4]   += wv.x * a; part[e4*4+1] += wv.y * a;
            part[e4*4+2] += wv.z * a; part[e4*4+3] += wv.w * a;
        }
    }

    if (h > 0) {
        #pragma unroll
        for (int e = 0; e < D; e++)
            s_part[(h - 1) * NW * DR + w * DR + e] = part[e];
    }
    __syncthreads();
    if (h == 0) {
        #pragma unroll
        for (int s = 0; s < HEADS - 1; s++)
            #pragma unroll
            for (int e = 0; e < D; e++)
                part[e] += s_part[s * NW * DR + w * DR + e];

        float4* outb = out4 + (size_t)b * IMGPIX;
        const int wi = wi0 + lwi, wj = wj0 + lwj;
        #pragma unroll
        for (int pi = 0; pi < 2; pi++)
            #pragma unroll
            for (int pj = 0; pj < 2; pj++) {
                int idx = pi * 2 + pj;
                outb[(wi * 2 + pi) * IMGW + (wj * 2 + pj)] =
                    make_float4(part[idx], part[4 + idx], part[8 + idx], 0.f);
            }
    }
}

// ============================================================================
// p=3 stage (per-batch launch): one warp-group per head; float4 window rows.
// (two-pass softmax — unchanged from the 73.8us best)
// ============================================================================
#define A3_TW 8
#define A3_TH 8
__global__ void __launch_bounds__(A3_TW*A3_TH*2)
attn3_kernel(int bbase,
             const float4* __restrict__ in4, float4* __restrict__ out4,
             const float4* __restrict__ Gt, const float4* __restrict__ gbp,
             const float4* __restrict__ Wvt, const float4* __restrict__ bvp)
{
    constexpr int D = 27, HEADS = 2;
    constexpr int DP = 28, DP4 = 7;
    constexpr int DR = 27;                      // odd
    constexpr int NW = A3_TW * A3_TH;           // 64
    constexpr int NTHR = NW * HEADS;            // 128
    constexpr int TILEH = (A3_TH + 2) * 3;      // 30
    constexpr int ROWW4 = 12;
    constexpr int CPLANE = TILEH * ROWW4 * 4;   // floats per channel plane
    constexpr int ELEMS = TILEH * 30;           // 900
    constexpr int ITERS = 8;

    __shared__ __align__(16) float4 s_t4[CH * TILEH * ROWW4];
    __shared__ float s_part[(HEADS - 1) * NW * DR];

    const int tid = threadIdx.x;
    const int b   = bbase;
    const int wi0 = blockIdx.y * A3_TH;
    const int wj0 = blockIdx.x * A3_TW;

    const float4* inb = in4 + (size_t)b * IMGPIX;
    float* s_tf = (float*)s_t4;
    #pragma unroll
    for (int k = 0; k < ITERS; k++) {
        int i = tid + k * NTHR;
        if (k == ITERS - 1 && i >= ELEMS) continue;
        int tr = i / 30, tc = i % 30;
        int off = reflect_h((wi0 - 1) * 3 + tr) * IMGW + reflect_w((wj0 - 1) * 3 + tc);
        int sm  = tr * (ROWW4 * 4) + (tc / 3) * 4 + tc % 3;
        float4 v = inb[off];
        s_tf[sm] = v.x;
        s_tf[CPLANE + sm] = v.y;
        s_tf[2 * CPLANE + sm] = v.z;
    }
    __syncthreads();

    const int w   = tid % NW;
    const int h   = tid / NW;
    const int lwj = w % A3_TW;
    const int lwi = w / A3_TW;

    float tok4[D];
    #pragma unroll
    for (int c = 0; c < CH; c++)
        #pragma unroll
        for (int pi = 0; pi < 3; pi++) {
            float4 v = s_t4[(c * TILEH + (lwi + 1) * 3 + pi) * ROWW4 + (lwj + 1)];
            int e = c * 9 + pi * 3;
            tok4[e] = v.x; tok4[e+1] = v.y; tok4[e+2] = v.z;
        }

    float u[DP];
    #pragma unroll
    for (int e4 = 0; e4 < DP4; e4++) {
        float4 v = gbp[h * DP4 + e4];
        u[e4*4] = v.x; u[e4*4+1] = v.y; u[e4*4+2] = v.z; u[e4*4+3] = v.w;
    }
    #pragma unroll
    for (int m = 0; m < D; m++) {
        float t = tok4[m];
        #pragma unroll
        for (int e4 = 0; e4 < DP4; e4++) {
            float4 g = Gt[(h * D + m) * DP4 + e4];
            u[e4*4]   += g.x * t; u[e4*4+1] += g.y * t;
            u[e4*4+2] += g.z * t; u[e4*4+3] += g.w * t;
        }
    }

    float sc[9];
    float smax = neg_inf();
    #pragma unroll
    for (int di = 0; di < 3; di++)
    #pragma unroll
    for (int dj = 0; dj < 3; dj++) {
        float s = 0.f;
        #pragma unroll
        for (int c = 0; c < CH; c++)
            #pragma unroll
            for (int pi = 0; pi < 3; pi++) {
                float4 v = s_t4[(c * TILEH + (lwi + di) * 3 + pi) * ROWW4 + (lwj + dj)];
                int e = c * 9 + pi * 3;
                s += u[e] * v.x + u[e+1] * v.y + u[e+2] * v.z;
            }
        sc[di * 3 + dj] = s;
        smax = fmaxf(smax, s);
    }

    float den = 0.f;
    #pragma unroll
    for (int t = 0; t < 9; t++) { float e = __expf(sc[t] - smax); sc[t] = e; den += e; }
    float inv = 1.f / den;
    #pragma unroll
    for (int t = 0; t < 9; t++) sc[t] *= inv;

    float acc[D];
    #pragma unroll
    for (int d = 0; d < D; d++) acc[d] = 0.f;
    #pragma unroll
    for (int di = 0; di < 3; di++)
    #pragma unroll
    for (int dj = 0; dj < 3; dj++) {
        const float a = sc[di * 3 + dj];
        #pragma unroll
        for (int c = 0; c < CH; c++)
            #pragma unroll
            for (int pi = 0; pi < 3; pi++) {
                float4 v = s_t4[(c * TILEH + (lwi + di) * 3 + pi) * ROWW4 + (lwj + dj)];
                int e = c * 9 + pi * 3;
                acc[e] += a * v.x; acc[e+1] += a * v.y; acc[e+2] += a * v.z;
            }
    }

    float part[DP];
    #pragma unroll
    for (int e4 = 0; e4 < DP4; e4++) {
        float4 v = bvp[h * DP4 + e4];
        part[e4*4] = v.x; part[e4*4+1] = v.y; part[e4*4+2] = v.z; part[e4*4+3] = v.w;
    }
    #pragma unroll
    for (int m = 0; m < D; m++) {
        float a = acc[m];
        #pragma unroll
        for (int e4 = 0; e4 < DP4; e4++) {
            float4 wv = Wvt[(h * D + m) * DP4 + e4];
            part[e4*4]   += wv.x * a; part[e4*4+1] += wv.y * a;
            part[e4*4+2] += wv.z * a; part[e4*4+3] += wv.w * a;
        }
    }

    if (h > 0) {
        #pragma unroll
        for (int e = 0; e < D; e++)
            s_part[(h - 1) * NW * DR + w * DR + e] = part[e];
    }
    __syncthreads();
    if (h == 0) {
        #pragma unroll
        for (int s = 0; s < HEADS - 1; s++)
            #pragma unroll
            for (int e = 0; e < D; e++)
                part[e] += s_part[s * NW * DR + w * DR + e];

        float4* outb = out4 + (size_t)b * IMGPIX;
        const int wi = wi0 + lwi, wj = wj0 + lwj;
        #pragma unroll
        for (int pi = 0; pi < 3; pi++)
            #pragma unroll
            for (int pj = 0; pj < 3; pj++) {
                int idx = pi * 3 + pj;
                outb[(wi * 3 + pi) * IMGW + (wj * 3 + pj)] =
                    make_float4(part[idx], part[9 + idx], part[18 + idx], 0.f);
            }
    }
}

// ============================================================================
// fused conv0 (5x5, zero pad 2, cat[x9,x6,x3]) + dehaze epilogue.
// Per-batch launch: batch b's final starts as soon as ITS chain finishes.
// ============================================================================
#define FB_X 8    // threads in x (each does 4 px)
#define FB_Y 16
#define FOUT_X 32
#define FOUT_Y 16

__global__ void __launch_bounds__(FB_X*FB_Y*3)
final_kernel(int bbase,
             const float* __restrict__ x,
             const float* __restrict__ conv_w, const float* __restrict__ conv_b,
             float* __restrict__ out)
{
    constexpr int TEH = FOUT_Y + 4, TEW = FOUT_X + 4;   // 20 x 36
    constexpr int NTHR = FB_X * FB_Y * 3;               // 384
    constexpr int CELEM = TEH * TEW;                    // 720 per channel
    __shared__ __align__(16) float s_t[9][TEH][TEW];
    __shared__ __align__(16) float s_w4[3][9][5][8];    // weight rows padded to 8
    __shared__ float s_b[3];
    __shared__ float s_red[NTHR / 32];

    const int tid = (threadIdx.z * FB_Y + threadIdx.y) * FB_X + threadIdx.x;
    for (int i = tid; i < 675; i += NTHR) {
        int co = i / 225; int r = i % 225; int ci = r / 25; int kk = r % 25;
        s_w4[co][ci][kk / 5][kk % 5] = conv_w[i];
    }
    if (tid < 3) s_b[tid] = conv_b[tid];

    const int b  = bbase;
    const int y0 = blockIdx.y * FOUT_Y;
    const int x0 = blockIdx.x * FOUT_X;

    // xg = image max (reduced from p=1 per-block maxes of THIS batch)
    float m = neg_inf();
    for (int i = tid; i < NB1; i += NTHR) m = fmaxf(m, g_bmax[b * NB1 + i]);
    #pragma unroll
    for (int o = 16; o; o >>= 1) m = fmaxf(m, __shfl_xor_sync(0xffffffffu, m, o));
    if ((tid & 31) == 0) s_red[tid >> 5] = m;

    // ---- halo tile load from channel-interleaved planes ----
    {
        const float4* p9 = g_x9v + (size_t)b * IMGPIX;
        const float4* p6 = g_x6v + (size_t)b * IMGPIX;
        const float4* p3 = g_x3v + (size_t)b * IMGPIX;

        #pragma unroll
        for (int k = 0; k < 2; k++) {
            int j = tid + k * NTHR;
            if (k == 1 && j >= CELEM) break;
            int ty = j / TEW, tx = j % TEW;
            int gy = y0 + ty - 2, gx = x0 + tx - 2;
            bool vld = (gy >= 0 && gy < IMGH && gx >= 0 && gx < IMGW);
            float4 f9 = make_float4(0.f, 0.f, 0.f, 0.f), f6 = f9, f3 = f9;
            if (vld) {
                int off = gy * IMGW + gx;
                f9 = p9[off]; f6 = p6[off]; f3 = p3[off];
            }
            (&s_t[0][0][0])[j] = f9.x; (&s_t[1][0][0])[j] = f9.y; (&s_t[2][0][0])[j] = f9.z;
            (&s_t[3][0][0])[j] = f6.x; (&s_t[4][0][0])[j] = f6.y; (&s_t[5][0][0])[j] = f6.z;
            (&s_t[6][0][0])[j] = f3.x; (&s_t[7][0][0])[j] = f3.y; (&s_t[8][0][0])[j] = f3.z;
        }
    }
    __syncthreads();

    float xg = s_red[0];
    #pragma unroll
    for (int w = 1; w < NTHR / 32; w++) xg = fmaxf(xg, s_red[w]);

    const int ty  = threadIdx.y;
    const int tx4 = threadIdx.x * 4;
    const int co  = threadIdx.z;

    float a0 = s_b[co], a1 = a0, a2 = a0, a3 = a0;

    #pragma unroll
    for (int ci = 0; ci < 9; ci++)
        #pragma unroll
        for (int kh = 0; kh < 5; kh++) {
            const float* rowp = &s_t[ci][ty + kh][tx4];
            float4 a = *(const float4*)(rowp);
            float4 c = *(const float4*)(rowp + 4);
            float rb[8] = {a.x, a.y, a.z, a.w, c.x, c.y, c.z, c.w};
            float4 w03 = *(const float4*)&s_w4[co][ci][kh][0];
            float  w4v = s_w4[co][ci][kh][4];
            float wv[5] = {w03.x, w03.y, w03.z, w03.w, w4v};
            #pragma unroll
            for (int kw = 0; kw < 5; kw++) {
                a0 += wv[kw] * rb[kw];
                a1 += wv[kw] * rb[kw + 1];
                a2 += wv[kw] * rb[kw + 2];
                a3 += wv[kw] * rb[kw + 3];
            }
        }

    const int gy = y0 + ty, gx = x0 + tx4;
    size_t idx = (((size_t)b * CH + co) * IMGH + gy) * IMGW + gx;
    float4 xv = *(const float4*)&x[idx];
    float4 r;
    float x0v;
    x0v = fmaxf(a0, 0.f); r.x = fmaxf(xv.x * x0v + (xg - x0v), 0.f);
    x0v = fmaxf(a1, 0.f); r.y = fmaxf(xv.y * x0v + (xg - x0v), 0.f);
    x0v = fmaxf(a2, 0.f); r.z = fmaxf(xv.z * x0v + (xg - x0v), 0.f);
    x0v = fmaxf(a3, 0.f); r.w = fmaxf(xv.w * x0v + (xg - x0v), 0.f);
    *(float4*)&out[idx] = r;
}

// ---------------- launch ----------------------------------------------------
extern "C" void kernel_launch(void* const* d_in, const int* in_sizes, int n_in,
                              void* d_out, int out_size)
{
    (void)in_sizes; (void)n_in; (void)out_size;

    const float* x    = (const float*)d_in[0];
    const float* w3q  = (const float*)d_in[1];
    const float* b3q  = (const float*)d_in[2];
    const float* w3k  = (const float*)d_in[3];
    const float* w3v  = (const float*)d_in[5];
    const float* b3v  = (const float*)d_in[6];
    const float* hw3  = (const float*)d_in[7];
    const float* w6q  = (const float*)d_in[8];
    const float* b6q  = (const float*)d_in[9];
    const float* w6k  = (const float*)d_in[10];
    const float* w6v  = (const float*)d_in[12];
    const float* b6v  = (const float*)d_in[13];
    const float* hw6  = (const float*)d_in[14];
    const float* w9q  = (const float*)d_in[15];
    const float* b9q  = (const float*)d_in[16];
    const float* w9k  = (const float*)d_in[17];
    const float* w9v  = (const float*)d_in[19];
    const float* b9v  = (const float*)d_in[20];
    const float* hw9  = (const float*)d_in[21];
    const float* cw   = (const float*)d_in[22];
    const float* cb   = (const float*)d_in[23];

    float4 *x3v, *x6v, *x9v;
    cudaGetSymbolAddress((void**)&x3v, g_x3v);
    cudaGetSymbolAddress((void**)&x6v, g_x6v);
    cudaGetSymbolAddress((void**)&x9v, g_x9v);
    float4 *G6, *gb6, *Wv6, *bv6, *G9, *gb9, *Wv9, *bv9;
    cudaGetSymbolAddress((void**)&G6,  g_G6t);
    cudaGetSymbolAddress((void**)&gb6, g_gb6);
    cudaGetSymbolAddress((void**)&Wv6, g_Wv6t);
    cudaGetSymbolAddress((void**)&bv6, g_bv6);
    cudaGetSymbolAddress((void**)&G9,  g_G9t);
    cudaGetSymbolAddress((void**)&gb9, g_gb9);
    cudaGetSymbolAddress((void**)&Wv9, g_Wv9t);
    cudaGetSymbolAddress((void**)&bv9, g_bv9);

    cudaStream_t s0 = 0;
    cudaStream_t s1 = g_pipe.s1;

    // fork: batch-1 chain runs on s1, batch-0 chain on the main stream
    cudaEventRecord(g_pipe.evFork, s0);
    cudaStreamWaitEvent(s1, g_pipe.evFork, 0);

    attn1_kernel<<<dim3(24, 24, 1), A1_TW * A1_TH, 0, s0>>>(
        0, x, x3v, w3q, b3q, w3k, w3v, b3v, hw3,
        w6q, b6q, w6k, w6v, b6v, hw6,
        w9q, b9q, w9k, w9v, b9v, hw9);
    attn1_kernel<<<dim3(24, 24, 1), A1_TW * A1_TH, 0, s1>>>(
        1, x, x3v, w3q, b3q, w3k, w3v, b3v, hw3,
        w6q, b6q, w6k, w6v, b6v, hw6,
        w9q, b9q, w9k, w9v, b9v, hw9);

    attn2_kernel<<<dim3(24, 24, 1), A2_TW * A2_TH * 4, 0, s0>>>(0, x3v, x6v, G6, gb6, Wv6, bv6);
    attn2_kernel<<<dim3(24, 24, 1), A2_TW * A2_TH * 4, 0, s1>>>(1, x3v, x6v, G6, gb6, Wv6, bv6);

    attn3_kernel<<<dim3(16, 16, 1), A3_TW * A3_TH * 2, 0, s0>>>(0, x6v, x9v, G9, gb9, Wv9, bv9);
    attn3_kernel<<<dim3(16, 16, 1), A3_TW * A3_TH * 2, 0, s1>>>(1, x6v, x9v, G9, gb9, Wv9, bv9);

    // per-batch final: each batch's epilogue runs in its own chain's stream
    final_kernel<<<dim3(IMGW / FOUT_X, IMGH / FOUT_Y, 1), dim3(FB_X, FB_Y, 3), 0, s0>>>(
        0, x, cw, cb, (float*)d_out);
    final_kernel<<<dim3(IMGW / FOUT_X, IMGH / FOUT_Y, 1), dim3(FB_X, FB_Y, 3), 0, s1>>>(
        1, x, cw, cb, (float*)d_out);

    // join: the capture stream must see batch 1's completion
    cudaEventRecord(g_pipe.evJoin, s1);
    cudaStreamWaitEvent(s0, g_pipe.evJoin, 0);
}